// round 12
// baseline (speedup 1.0000x reference)
#include <cuda_runtime.h>
#include <cstdint>
#include <cstddef>

// Problem constants (fixed by the reference)
#define BB    4
#define NN    4096
#define FIN   256
#define FOUT  64
#define ALPHA 0.2f
#define NT    64              // j-tiles of 64

using u64 = unsigned long long;

// Scratch (device globals: no allocation allowed)
__device__ float g_Wh [BB * NN * FOUT];     // 4 MB, [b*N + j][f]
__device__ float g_Wh1[BB * NN];
__device__ float g_Wh2[BB * NN];
__device__ float g_max2[BB];
__device__ float g_eA[BB * NN];             // exp(w1 - m_i)
__device__ float g_eC[BB * NN];             // exp(a*w1 - m_i)
__device__ float g_eB[BB * NN];             // exp(w2)
__device__ float g_eD[BB * NN];             // exp(a*w2)
// Packed fragment-ready B (permuted unit order): per (b,t) 1024 x 16B = 16KB
__device__ float g_Bpk[BB * NT * 4096];     // 4 MB

// ---------- packed f32x2 helpers (k_proj) ----------
__device__ __forceinline__ u64 pk2(float lo, float hi) {
    u64 r; asm("mov.b64 %0, {%1, %2};" : "=l"(r) : "f"(lo), "f"(hi)); return r;
}
__device__ __forceinline__ u64 fma2(u64 a, u64 b, u64 c) {
    u64 d; asm("fma.rn.f32x2 %0, %1, %2, %3;" : "=l"(d) : "l"(a), "l"(b), "l"(c)); return d;
}
__device__ __forceinline__ float2 upk2(u64 v) {
    float2 r; asm("mov.b64 {%0, %1}, %2;" : "=f"(r.x), "=f"(r.y) : "l"(v)); return r;
}

// bf16x2 pack: bits[31:16]=bf16(hi), bits[15:0]=bf16(lo)
__device__ __forceinline__ uint32_t cvt2(float hi, float lo) {
    uint32_t r; asm("cvt.rn.bf16x2.f32 %0, %1, %2;" : "=r"(r) : "f"(hi), "f"(lo)); return r;
}

// m16n8k16 bf16 MMA (baseline sm_80 ISA — compiles at compute_100)
__device__ __forceinline__ void mma_bf16(float* d, uint32_t a0, uint32_t a1,
                                         uint32_t a2, uint32_t a3,
                                         uint32_t b0, uint32_t b1) {
    asm volatile(
        "mma.sync.aligned.m16n8k16.row.col.f32.bf16.bf16.f32 "
        "{%0,%1,%2,%3}, {%4,%5,%6,%7}, {%8,%9}, {%0,%1,%2,%3};"
        : "+f"(d[0]), "+f"(d[1]), "+f"(d[2]), "+f"(d[3])
        : "r"(a0), "r"(a1), "r"(a2), "r"(a3), "r"(b0), "r"(b1));
}

__device__ __forceinline__ void cp16(uint32_t saddr, const void* g) {
    asm volatile("cp.async.cg.shared.global [%0], [%1], 16;"
                 :: "r"(saddr), "l"(g) : "memory");
}

// Order-independent (deterministic) float atomic max.
__device__ __forceinline__ void atomicMaxFloat(float* addr, float v) {
    if (v >= 0.f) atomicMax((int*)addr,          __float_as_int(v));
    else          atomicMin((unsigned int*)addr, __float_as_uint(v));
}

// ---------------------------------------------------------------------------
// K_init
// ---------------------------------------------------------------------------
__global__ void k_init() {
    if (threadIdx.x < BB) g_max2[threadIdx.x] = -3.0e38f;
}

// ---------------------------------------------------------------------------
// K_proj: tiled GEMM  Wh = h @ W + bias, fused Wh1/Wh2 dots + per-batch max.
// ---------------------------------------------------------------------------
__global__ void __launch_bounds__(256, 2)
k_proj(const float* __restrict__ h, const float* __restrict__ W,
       const float* __restrict__ a, const float* __restrict__ bias) {
    __shared__ __align__(16) float sH[64 * 68];
    __shared__ __align__(16) float sW[64 * 64];

    int tid = threadIdx.x;
    int ti = tid >> 4;
    int jq = tid & 15;
    int i0 = blockIdx.x * 64;

    u64 acc[4][2];
#pragma unroll
    for (int r = 0; r < 4; r++) { acc[r][0] = 0ull; acc[r][1] = 0ull; }

    for (int kc = 0; kc < 4; kc++) {
        int k0 = kc * 64;
#pragma unroll
        for (int u = 0; u < 4; u++) {
            int q = tid + u * 256;
            int row = q >> 4, c4 = q & 15;
            *(float4*)(sH + row * 68 + c4 * 4) =
                *(const float4*)(h + (size_t)(i0 + row) * FIN + k0 + c4 * 4);
            *(float4*)(sW + row * 64 + c4 * 4) =
                *(const float4*)(W + (size_t)(k0 + row) * FOUT + c4 * 4);
        }
        __syncthreads();

#pragma unroll 4
        for (int k = 0; k < 64; k++) {
            ulonglong2 wv = *(const ulonglong2*)(sW + k * 64 + 4 * jq);
#pragma unroll
            for (int r = 0; r < 4; r++) {
                float hv = sH[(ti * 4 + r) * 68 + k];
                u64 hh = pk2(hv, hv);
                acc[r][0] = fma2(hh, wv.x, acc[r][0]);
                acc[r][1] = fma2(hh, wv.y, acc[r][1]);
            }
        }
        __syncthreads();
    }

    float4 bv = *(const float4*)(bias + 4 * jq);
    float4 a1 = *(const float4*)(a + 4 * jq);
    float4 a2 = *(const float4*)(a + FOUT + 4 * jq);
    float p1[4], p2[4];
#pragma unroll
    for (int r = 0; r < 4; r++) {
        float2 v01 = upk2(acc[r][0]), v23 = upk2(acc[r][1]);
        float4 wh = make_float4(v01.x + bv.x, v01.y + bv.y,
                                v23.x + bv.z, v23.y + bv.w);
        int grow = i0 + ti * 4 + r;
        *(float4*)(g_Wh + (size_t)grow * FOUT + 4 * jq) = wh;
        p1[r] = wh.x * a1.x + wh.y * a1.y + wh.z * a1.z + wh.w * a1.w;
        p2[r] = wh.x * a2.x + wh.y * a2.y + wh.z * a2.z + wh.w * a2.w;
    }

    float* sR1 = sH;
    float* sR2 = sH + 1024;
#pragma unroll
    for (int r = 0; r < 4; r++) {
        sR1[jq * 64 + ti * 4 + r] = p1[r];
        sR2[jq * 64 + ti * 4 + r] = p2[r];
    }
    __syncthreads();
    if (tid < 64) {
        float w1 = 0.f, w2 = 0.f;
#pragma unroll
        for (int q = 0; q < 16; q++) {
            w1 += sR1[q * 64 + tid];
            w2 += sR2[q * 64 + tid];
        }
        g_Wh1[i0 + tid] = w1;
        g_Wh2[i0 + tid] = w2;
        float m = w2;
#pragma unroll
        for (int o = 16; o > 0; o >>= 1)
            m = fmaxf(m, __shfl_xor_sync(0xFFFFFFFFu, m, o));
        if ((tid & 31) == 0) atomicMaxFloat(&g_max2[i0 >> 12], m);
    }
}

// ---------------------------------------------------------------------------
// K_prep_pack: (a) factored attention exponentials (first 16384 threads);
// (b) one-time bf16 hi/lo fragment packing of Wh, stored in a PHASE-AWARE
// PERMUTED unit order so k_attn's LDS.128 reads are bank-conflict-free:
//   unit16(r, c, nb, kb) = (r&1) | c<<1 | (r>>1)<<3 | nb<<5 | kb<<8
// where f = nb*8 + r (feature), kb = k16 block, c = k-quad.
// Unit content (16B): {Bh(k=2c,2c+1), Bh(2c+8,2c+9), Bl(2c,2c+1), Bl(2c+8,2c+9)}
// with j-permutation j_local=4c+m -> k: m0->2c, m1->2c+1, m2->2c+8, m3->2c+9.
// ---------------------------------------------------------------------------
__global__ void k_prep_pack() {
    int idx = blockIdx.x * blockDim.x + threadIdx.x;   // 262144

    if (idx < BB * NN) {
        int b = idx >> 12;
        float mx = g_max2[b];
        float w1 = g_Wh1[idx];
        float w2 = g_Wh2[idx];
        float e = w1 + mx;
        float m = fmaxf(e, ALPHA * e);     // m_i >= all e_ij
        g_eA[idx] = __expf(w1 - m);
        g_eC[idx] = __expf(ALPHA * w1 - m);
        g_eB[idx] = __expf(w2);
        g_eD[idx] = __expf(ALPHA * w2);
    }

    int f    = idx & 63;
    int c    = (idx >> 6) & 3;
    int kb   = (idx >> 8) & 3;
    int t    = (idx >> 10) & 63;
    int b    = idx >> 16;

    int j0 = t * 64 + kb * 16 + 4 * c;
    const float* src = g_Wh + (size_t)(b * NN + j0) * FOUT + f;
    float v0 = src[0];
    float v1 = src[FOUT];
    float v2 = src[2 * FOUT];
    float v3 = src[3 * FOUT];

    uint32_t h01 = cvt2(v1, v0);          // k=2c, 2c+1
    uint32_t h23 = cvt2(v3, v2);          // k=2c+8, 2c+9
    float l0 = v0 - __uint_as_float(h01 << 16);
    float l1 = v1 - __uint_as_float(h01 & 0xFFFF0000u);
    float l2 = v2 - __uint_as_float(h23 << 16);
    float l3 = v3 - __uint_as_float(h23 & 0xFFFF0000u);
    uint32_t lo01 = cvt2(l1, l0);
    uint32_t lo23 = cvt2(l3, l2);

    int r  = f & 7;
    int nb = f >> 3;
    int u16 = (r & 1) | (c << 1) | ((r >> 1) << 3) | (nb << 5) | (kb << 8);
    size_t u = ((size_t)(b * NT + t) * 1024) + (size_t)u16;
    *(uint4*)(g_Bpk + u * 4) = make_uint4(h01, h23, lo01, lo23);
}

// ---------------------------------------------------------------------------
// A-fragment builder: one row's 4 j's -> masked factored softmax weights,
// bf16 hi/lo packed pairs. ls accumulates the (pre-split) p values.
// ---------------------------------------------------------------------------
struct AF { uint32_t ha, hb, la, lb; };
__device__ __forceinline__ AF build_row(float eA, float eC, int4 A,
                                        float4 vB, float4 vD, float& ls) {
    float p0 = (A.x > 0) ? fmaxf(eA * vB.x, eC * vD.x) : 0.f;
    float p1 = (A.y > 0) ? fmaxf(eA * vB.y, eC * vD.y) : 0.f;
    float p2 = (A.z > 0) ? fmaxf(eA * vB.z, eC * vD.z) : 0.f;
    float p3 = (A.w > 0) ? fmaxf(eA * vB.w, eC * vD.w) : 0.f;
    ls += (p0 + p1) + (p2 + p3);
    AF o;
    o.ha = cvt2(p1, p0);
    o.hb = cvt2(p3, p2);
    float l0 = p0 - __uint_as_float(o.ha << 16);
    float l1 = p1 - __uint_as_float(o.ha & 0xFFFF0000u);
    float l2 = p2 - __uint_as_float(o.hb << 16);
    float l3 = p3 - __uint_as_float(o.hb & 0xFFFF0000u);
    o.la = cvt2(l1, l0);
    o.lb = cvt2(l3, l2);
    return o;
}

// ---------------------------------------------------------------------------
// K_attn: fused masked-softmax attention; PV on m16n8k16 bf16 (3-pass hi/lo).
// CTA: 128 thr / 4 warps / 64 rows; warp w owns rows w*16..+15 x all 64 feats.
// BOTH the packed B operand AND the adjacency stream through 3-stage cp.async
// smem rings (16 KB/tile each). adj is PERMUTED at the cp.async destination
// into the same phase-aware unit order as B, so every in-loop LDS.128 is
// bank-conflict-free. Dynamic smem 96 KB -> 2 CTAs/SM -> grid 256 = 1 wave.
// ---------------------------------------------------------------------------
#define SMEM_ATTN (6 * 16384)

__global__ void __launch_bounds__(128)
k_attn(const int* __restrict__ adj, float* __restrict__ out) {
    extern __shared__ __align__(16) float smemf[];
    float* sB = smemf;                     // 3 x 4096 floats (B ring)
    float* sA = smemf + 3 * 4096;          // 3 x 4096 floats (adj ring)
    uint32_t sbB = (uint32_t)__cvta_generic_to_shared(sB);
    uint32_t sbA = (uint32_t)__cvta_generic_to_shared(sA);

    int tid  = threadIdx.x;
    int lane = tid & 31;
    int w    = tid >> 5;
    int b    = blockIdx.x >> 6;                 // 64 blocks per batch
    int i0   = (blockIdx.x & 63) * 64;
    int r    = lane >> 2;                       // 0..7
    int c    = lane & 3;                        // 0..3

    int row0 = b * NN + i0 + w * 16 + r;        // global row (and +8)
    float eA0 = g_eA[row0],     eC0 = g_eC[row0];
    float eA1 = g_eA[row0 + 8], eC1 = g_eC[row0 + 8];

    const int*   apc = adj + (size_t)(b * NN + i0) * NN;   // CTA adj base
    const float* eBp = g_eB + b * NN;
    const float* eDp = g_eD + b * NN;
    const float* gB  = g_Bpk + (size_t)(b * NT) * 4096;

    // Per-thread adj copy slots: unit L = tid + i*128 -> (row, u) -> permuted dest
    int aRow[8]; uint32_t aDst[8]; int aOff[8];
#pragma unroll
    for (int i = 0; i < 8; i++) {
        int L = tid + i * 128;
        int row = L >> 4, u = L & 15;
        int cc = u & 3, kk = u >> 2;
        int ww = row >> 4, hb = (row >> 3) & 1, r3 = row & 7;
        int d16 = (r3 & 1) | (cc << 1) | ((r3 >> 1) << 3) | (kk << 5) |
                  (hb << 7) | (ww << 8);
        aRow[i] = row; aDst[i] = (uint32_t)(d16 << 4); aOff[i] = u * 4;
    }

    // Consumer lane bases (permuted unit indices, in float offsets = u16*4)
    int aL = ((r & 1) | (c << 1) | ((r >> 1) << 3) | (w << 8)) << 2;
    int bL = ((r & 1) | (c << 1) | ((r >> 1) << 3)) << 2;

    float acc[8][4];
#pragma unroll
    for (int nb = 0; nb < 8; nb++)
#pragma unroll
        for (int q = 0; q < 4; q++) acc[nb][q] = 0.f;
    float ls0 = 0.f, ls1 = 0.f;

    // Prologue: stage tiles 0 and 1 (B + adj each)
#pragma unroll
    for (int pt = 0; pt < 2; pt++) {
#pragma unroll
        for (int i = 0; i < 8; i++)
            cp16(sbB + pt * 16384 + (tid + i * 128) * 16,
                 gB + (size_t)pt * 4096 + (size_t)(tid + i * 128) * 4);
#pragma unroll
        for (int i = 0; i < 8; i++)
            cp16(sbA + pt * 16384 + aDst[i],
                 apc + (size_t)aRow[i] * NN + pt * 64 + aOff[i]);
        asm volatile("cp.async.commit_group;" ::: "memory");
    }

    for (int t = 0; t < NT; t++) {
        asm volatile("cp.async.wait_group 1;" ::: "memory");
        __syncthreads();

        // Stage tile t+2 into the ring slot freed by compute(t-1)
        if (t + 2 < NT) {
            int s = (t + 2) % 3;
            const float* gsrc = gB + (size_t)(t + 2) * 4096;
#pragma unroll
            for (int i = 0; i < 8; i++)
                cp16(sbB + s * 16384 + (tid + i * 128) * 16,
                     gsrc + (size_t)(tid + i * 128) * 4);
#pragma unroll
            for (int i = 0; i < 8; i++)
                cp16(sbA + s * 16384 + aDst[i],
                     apc + (size_t)aRow[i] * NN + (t + 2) * 64 + aOff[i]);
        }
        asm volatile("cp.async.commit_group;" ::: "memory");

        const float* bB = sB + (t % 3) * 4096;
        const float* bA = sA + (t % 3) * 4096;
        int jt = t * 64;

#pragma unroll
        for (int kb = 0; kb < 4; kb++) {
            int jc = jt + kb * 16 + 4 * c;
            float4 vB = *(const float4*)(eBp + jc);
            float4 vD = *(const float4*)(eDp + jc);
            int4 A0 = *(const int4*)(bA + aL + (kb << 7));            // hb=0
            int4 A1 = *(const int4*)(bA + aL + (kb << 7) + 512);      // hb=1

            AF f0 = build_row(eA0, eC0, A0, vB, vD, ls0);
            AF f1 = build_row(eA1, eC1, A1, vB, vD, ls1);

            const float* bp = bB + bL + (kb << 10);
#pragma unroll
            for (int nb = 0; nb < 8; nb++) {
                float4 u = *(const float4*)(bp + (nb << 7));
                uint32_t Bh0 = __float_as_uint(u.x), Bh1 = __float_as_uint(u.y);
                uint32_t Bl0 = __float_as_uint(u.z), Bl1 = __float_as_uint(u.w);
                mma_bf16(acc[nb], f0.ha, f1.ha, f0.hb, f1.hb, Bh0, Bh1);
                mma_bf16(acc[nb], f0.ha, f1.ha, f0.hb, f1.hb, Bl0, Bl1);
                mma_bf16(acc[nb], f0.la, f1.la, f0.lb, f1.lb, Bh0, Bh1);
            }
        }
    }

    // Deterministic row-sum reduce within each k-quad (warp-local rows)
    ls0 += __shfl_xor_sync(0xFFFFFFFFu, ls0, 1);
    ls0 += __shfl_xor_sync(0xFFFFFFFFu, ls0, 2);
    ls1 += __shfl_xor_sync(0xFFFFFFFFu, ls1, 1);
    ls1 += __shfl_xor_sync(0xFFFFFFFFu, ls1, 2);

    // Epilogue: softmax divide, ELU, store
    float inv0 = 1.0f / ls0;
    float inv1 = 1.0f / ls1;
    float* o0 = out + (size_t)row0 * FOUT;
    float* o1 = out + (size_t)(row0 + 8) * FOUT;
#pragma unroll
    for (int nb = 0; nb < 8; nb++) {
        int col = nb * 8 + 2 * c;
        float x0 = acc[nb][0] * inv0, x1 = acc[nb][1] * inv0;
        float x2 = acc[nb][2] * inv1, x3 = acc[nb][3] * inv1;
        float2 oA, oB;
        oA.x = (x0 > 0.f) ? x0 : expm1f(x0);
        oA.y = (x1 > 0.f) ? x1 : expm1f(x1);
        oB.x = (x2 > 0.f) ? x2 : expm1f(x2);
        oB.y = (x3 > 0.f) ? x3 : expm1f(x3);
        *(float2*)(o0 + col) = oA;
        *(float2*)(o1 + col) = oB;
    }
}

// ---------------------------------------------------------------------------
// Inputs (metadata order): h[f32], adj[i32], W[f32], a[f32], bias[f32]
// Launch group is 4 kernels: ncu (-s 5, 2 pre-launch groups) captures
// index 3 = k_attn.
// ---------------------------------------------------------------------------
extern "C" void kernel_launch(void* const* d_in, const int* in_sizes, int n_in,
                              void* d_out, int out_size) {
    const float* h    = (const float*)d_in[0];
    const int*   adj  = (const int*)  d_in[1];
    const float* W    = (const float*)d_in[2];
    const float* a    = (const float*)d_in[3];
    const float* bias = (const float*)d_in[4];
    float* out = (float*)d_out;

    cudaFuncSetAttribute(k_attn, cudaFuncAttributeMaxDynamicSharedMemorySize,
                         SMEM_ATTN);

    k_init<<<1, 32>>>();
    k_proj<<<(BB * NN) / 64, 256>>>(h, W, a, bias);
    k_prep_pack<<<1024, 256>>>();
    k_attn<<<BB * (NN / 64), 128, SMEM_ATTN>>>(adj, out);
}

// round 14
// speedup vs baseline: 1.4900x; 1.4900x over previous
#include <cuda_runtime.h>
#include <cstdint>
#include <cstddef>

// Problem constants (fixed by the reference)
#define BB    4
#define NN    4096
#define FIN   256
#define FOUT  64
#define ALPHA 0.2f
#define NT    64              // j-tiles of 64

using u64 = unsigned long long;

// Scratch (device globals: no allocation allowed)
__device__ float g_Wh [BB * NN * FOUT];     // 4 MB, [b*N + j][f]
__device__ float g_Wh1[BB * NN];
__device__ float g_Wh2[BB * NN];
__device__ float g_max2[BB];
__device__ float g_eA[BB * NN];             // exp(w1 - m_i)
__device__ float g_eC[BB * NN];             // exp(a*w1 - m_i)
__device__ float g_eB[BB * NN];             // exp(w2)
__device__ float g_eD[BB * NN];             // exp(a*w2)
// Packed fragment-ready B (permuted unit order): per (b,t) 1024 x 16B = 16KB
__device__ float g_Bpk[BB * NT * 4096];     // 4 MB

// ---------- packed f32x2 helpers (k_proj) ----------
__device__ __forceinline__ u64 pk2(float lo, float hi) {
    u64 r; asm("mov.b64 %0, {%1, %2};" : "=l"(r) : "f"(lo), "f"(hi)); return r;
}
__device__ __forceinline__ u64 fma2(u64 a, u64 b, u64 c) {
    u64 d; asm("fma.rn.f32x2 %0, %1, %2, %3;" : "=l"(d) : "l"(a), "l"(b), "l"(c)); return d;
}
__device__ __forceinline__ float2 upk2(u64 v) {
    float2 r; asm("mov.b64 {%0, %1}, %2;" : "=f"(r.x), "=f"(r.y) : "l"(v)); return r;
}

// bf16x2 pack: bits[31:16]=bf16(hi), bits[15:0]=bf16(lo)
__device__ __forceinline__ uint32_t cvt2(float hi, float lo) {
    uint32_t r; asm("cvt.rn.bf16x2.f32 %0, %1, %2;" : "=r"(r) : "f"(hi), "f"(lo)); return r;
}

// m16n8k16 bf16 MMA (baseline sm_80 ISA — compiles at compute_100)
__device__ __forceinline__ void mma_bf16(float* d, uint32_t a0, uint32_t a1,
                                         uint32_t a2, uint32_t a3,
                                         uint32_t b0, uint32_t b1) {
    asm volatile(
        "mma.sync.aligned.m16n8k16.row.col.f32.bf16.bf16.f32 "
        "{%0,%1,%2,%3}, {%4,%5,%6,%7}, {%8,%9}, {%0,%1,%2,%3};"
        : "+f"(d[0]), "+f"(d[1]), "+f"(d[2]), "+f"(d[3])
        : "r"(a0), "r"(a1), "r"(a2), "r"(a3), "r"(b0), "r"(b1));
}

__device__ __forceinline__ void cp16(uint32_t saddr, const void* g) {
    asm volatile("cp.async.cg.shared.global [%0], [%1], 16;"
                 :: "r"(saddr), "l"(g) : "memory");
}

// Order-independent (deterministic) float atomic max.
__device__ __forceinline__ void atomicMaxFloat(float* addr, float v) {
    if (v >= 0.f) atomicMax((int*)addr,          __float_as_int(v));
    else          atomicMin((unsigned int*)addr, __float_as_uint(v));
}

// ---------------------------------------------------------------------------
// K_init
// ---------------------------------------------------------------------------
__global__ void k_init() {
    if (threadIdx.x < BB) g_max2[threadIdx.x] = -3.0e38f;
}

// ---------------------------------------------------------------------------
// K_proj: tiled GEMM  Wh = h @ W + bias, fused Wh1/Wh2 dots + per-batch max.
// ---------------------------------------------------------------------------
__global__ void __launch_bounds__(256, 2)
k_proj(const float* __restrict__ h, const float* __restrict__ W,
       const float* __restrict__ a, const float* __restrict__ bias) {
    __shared__ __align__(16) float sH[64 * 68];
    __shared__ __align__(16) float sW[64 * 64];

    int tid = threadIdx.x;
    int ti = tid >> 4;
    int jq = tid & 15;
    int i0 = blockIdx.x * 64;

    u64 acc[4][2];
#pragma unroll
    for (int r = 0; r < 4; r++) { acc[r][0] = 0ull; acc[r][1] = 0ull; }

    for (int kc = 0; kc < 4; kc++) {
        int k0 = kc * 64;
#pragma unroll
        for (int u = 0; u < 4; u++) {
            int q = tid + u * 256;
            int row = q >> 4, c4 = q & 15;
            *(float4*)(sH + row * 68 + c4 * 4) =
                *(const float4*)(h + (size_t)(i0 + row) * FIN + k0 + c4 * 4);
            *(float4*)(sW + row * 64 + c4 * 4) =
                *(const float4*)(W + (size_t)(k0 + row) * FOUT + c4 * 4);
        }
        __syncthreads();

#pragma unroll 4
        for (int k = 0; k < 64; k++) {
            ulonglong2 wv = *(const ulonglong2*)(sW + k * 64 + 4 * jq);
#pragma unroll
            for (int r = 0; r < 4; r++) {
                float hv = sH[(ti * 4 + r) * 68 + k];
                u64 hh = pk2(hv, hv);
                acc[r][0] = fma2(hh, wv.x, acc[r][0]);
                acc[r][1] = fma2(hh, wv.y, acc[r][1]);
            }
        }
        __syncthreads();
    }

    float4 bv = *(const float4*)(bias + 4 * jq);
    float4 a1 = *(const float4*)(a + 4 * jq);
    float4 a2 = *(const float4*)(a + FOUT + 4 * jq);
    float p1[4], p2[4];
#pragma unroll
    for (int r = 0; r < 4; r++) {
        float2 v01 = upk2(acc[r][0]), v23 = upk2(acc[r][1]);
        float4 wh = make_float4(v01.x + bv.x, v01.y + bv.y,
                                v23.x + bv.z, v23.y + bv.w);
        int grow = i0 + ti * 4 + r;
        *(float4*)(g_Wh + (size_t)grow * FOUT + 4 * jq) = wh;
        p1[r] = wh.x * a1.x + wh.y * a1.y + wh.z * a1.z + wh.w * a1.w;
        p2[r] = wh.x * a2.x + wh.y * a2.y + wh.z * a2.z + wh.w * a2.w;
    }

    float* sR1 = sH;
    float* sR2 = sH + 1024;
#pragma unroll
    for (int r = 0; r < 4; r++) {
        sR1[jq * 64 + ti * 4 + r] = p1[r];
        sR2[jq * 64 + ti * 4 + r] = p2[r];
    }
    __syncthreads();
    if (tid < 64) {
        float w1 = 0.f, w2 = 0.f;
#pragma unroll
        for (int q = 0; q < 16; q++) {
            w1 += sR1[q * 64 + tid];
            w2 += sR2[q * 64 + tid];
        }
        g_Wh1[i0 + tid] = w1;
        g_Wh2[i0 + tid] = w2;
        float m = w2;
#pragma unroll
        for (int o = 16; o > 0; o >>= 1)
            m = fmaxf(m, __shfl_xor_sync(0xFFFFFFFFu, m, o));
        if ((tid & 31) == 0) atomicMaxFloat(&g_max2[i0 >> 12], m);
    }
}

// ---------------------------------------------------------------------------
// K_prep_pack: (a) factored attention exponentials (first 16384 threads);
// (b) one-time bf16 hi/lo fragment packing of Wh in the PHASE-AWARE PERMUTED
// unit order (conflict-free LDS.128 in k_attn):
//   unit16(r, c, nb, kb) = (r&1) | c<<1 | (r>>1)<<3 | nb<<5 | kb<<8
// Unit content (16B): {Bh(k=2c,2c+1), Bh(2c+8,2c+9), Bl(2c,2c+1), Bl(2c+8,2c+9)}
// with j-permutation j_local=4c+m -> k: m0->2c, m1->2c+1, m2->2c+8, m3->2c+9.
// ---------------------------------------------------------------------------
__global__ void k_prep_pack() {
    int idx = blockIdx.x * blockDim.x + threadIdx.x;   // 262144

    if (idx < BB * NN) {
        int b = idx >> 12;
        float mx = g_max2[b];
        float w1 = g_Wh1[idx];
        float w2 = g_Wh2[idx];
        float e = w1 + mx;
        float m = fmaxf(e, ALPHA * e);     // m_i >= all e_ij
        g_eA[idx] = __expf(w1 - m);
        g_eC[idx] = __expf(ALPHA * w1 - m);
        g_eB[idx] = __expf(w2);
        g_eD[idx] = __expf(ALPHA * w2);
    }

    int f    = idx & 63;
    int c    = (idx >> 6) & 3;
    int kb   = (idx >> 8) & 3;
    int t    = (idx >> 10) & 63;
    int b    = idx >> 16;

    int j0 = t * 64 + kb * 16 + 4 * c;
    const float* src = g_Wh + (size_t)(b * NN + j0) * FOUT + f;
    float v0 = src[0];
    float v1 = src[FOUT];
    float v2 = src[2 * FOUT];
    float v3 = src[3 * FOUT];

    uint32_t h01 = cvt2(v1, v0);          // k=2c, 2c+1
    uint32_t h23 = cvt2(v3, v2);          // k=2c+8, 2c+9
    float l0 = v0 - __uint_as_float(h01 << 16);
    float l1 = v1 - __uint_as_float(h01 & 0xFFFF0000u);
    float l2 = v2 - __uint_as_float(h23 << 16);
    float l3 = v3 - __uint_as_float(h23 & 0xFFFF0000u);
    uint32_t lo01 = cvt2(l1, l0);
    uint32_t lo23 = cvt2(l3, l2);

    int r  = f & 7;
    int nb = f >> 3;
    int u16 = (r & 1) | (c << 1) | ((r >> 1) << 3) | (nb << 5) | (kb << 8);
    size_t u = ((size_t)(b * NT + t) * 1024) + (size_t)u16;
    *(uint4*)(g_Bpk + u * 4) = make_uint4(h01, h23, lo01, lo23);
}

// ---------------------------------------------------------------------------
// A-fragment builder: one row's 4 j's -> masked factored softmax weights,
// bf16 hi/lo packed pairs. ls accumulates the (pre-split) p values.
// ---------------------------------------------------------------------------
struct AF { uint32_t ha, hb, la, lb; };
__device__ __forceinline__ AF build_row(float eA, float eC, int4 A,
                                        float4 vB, float4 vD, float& ls) {
    float p0 = (A.x > 0) ? fmaxf(eA * vB.x, eC * vD.x) : 0.f;
    float p1 = (A.y > 0) ? fmaxf(eA * vB.y, eC * vD.y) : 0.f;
    float p2 = (A.z > 0) ? fmaxf(eA * vB.z, eC * vD.z) : 0.f;
    float p3 = (A.w > 0) ? fmaxf(eA * vB.w, eC * vD.w) : 0.f;
    ls += (p0 + p1) + (p2 + p3);
    AF o;
    o.ha = cvt2(p1, p0);
    o.hb = cvt2(p3, p2);
    float l0 = p0 - __uint_as_float(o.ha << 16);
    float l1 = p1 - __uint_as_float(o.ha & 0xFFFF0000u);
    float l2 = p2 - __uint_as_float(o.hb << 16);
    float l3 = p3 - __uint_as_float(o.hb & 0xFFFF0000u);
    o.la = cvt2(l1, l0);
    o.lb = cvt2(l3, l2);
    return o;
}

// ---------------------------------------------------------------------------
// K_attn: fused masked-softmax attention; PV on m16n8k16 bf16 (3-pass hi/lo).
// CTA: 128 thr / 4 warps / 64 rows; warp w owns rows w*16..+15 x all 64 feats.
// B (packed, permuted) + eB/eD factor slices stream via a 3-stage cp.async
// ring in DYNAMIC shared memory (50688 B > 48 KB static limit). Adjacency
// uses coalesced LDG.128 with a register double-buffer one full tile ahead
// (issued before the pipeline wait -> DRAM latency hidden by a whole tile of
// compute). eB/eD in-loop reads are conflict-free LDS.
// ---------------------------------------------------------------------------
#define SMEM_ATTN (3 * 16384 + 3 * 512)     // 50688 bytes (dynamic)

__global__ void __launch_bounds__(128)
k_attn(const int* __restrict__ adj, float* __restrict__ out) {
    extern __shared__ __align__(16) float smemf[];
    float* sB = smemf;                     // 3 x 4096 floats (B ring)
    float* sE = smemf + 3 * 4096;          // 3 x 128 floats (eB/eD ring)
    uint32_t sbB = (uint32_t)__cvta_generic_to_shared(sB);
    uint32_t sbE = (uint32_t)__cvta_generic_to_shared(sE);

    int tid  = threadIdx.x;
    int lane = tid & 31;
    int w    = tid >> 5;
    int b    = blockIdx.x >> 6;                 // 64 blocks per batch
    int i0   = (blockIdx.x & 63) * 64;
    int r    = lane >> 2;                       // 0..7
    int c    = lane & 3;                        // 0..3

    int row0 = b * NN + i0 + w * 16 + r;        // global row (and +8)
    float eA0 = g_eA[row0],     eC0 = g_eC[row0];
    float eA1 = g_eA[row0 + 8], eC1 = g_eC[row0 + 8];

    const int*   ap  = adj + (size_t)row0 * NN;
    const float* eBb = g_eB + b * NN;
    const float* eDb = g_eD + b * NN;
    const float* gB  = g_Bpk + (size_t)(b * NT) * 4096;

    // eB/eD ring copy source for this thread (tid<32 copies one 16B unit)
    const float* esrc = (tid < 16) ? (eBb + (tid & 15) * 4)
                                   : (eDb + (tid & 15) * 4);

    // Consumer lane base into permuted B units (float offset = u16*4)
    int bL = ((r & 1) | (c << 1) | ((r >> 1) << 3)) << 2;

    float acc[8][4];
#pragma unroll
    for (int nb = 0; nb < 8; nb++)
#pragma unroll
        for (int q = 0; q < 4; q++) acc[nb][q] = 0.f;
    float ls0 = 0.f, ls1 = 0.f;

    // Prologue: stage B+E tiles 0 and 1; load adj tile 0 into registers
#pragma unroll
    for (int pt = 0; pt < 2; pt++) {
#pragma unroll
        for (int i = 0; i < 8; i++)
            cp16(sbB + pt * 16384 + (tid + i * 128) * 16,
                 gB + (size_t)pt * 4096 + (size_t)(tid + i * 128) * 4);
        if (tid < 32)
            cp16(sbE + pt * 512 + tid * 16, esrc + pt * 64);
        asm volatile("cp.async.commit_group;" ::: "memory");
    }

    int4 avA[8], avB[8];
#pragma unroll
    for (int kb = 0; kb < 4; kb++) {
        int jc = kb * 16 + 4 * c;
        avA[2 * kb]     = *(const int4*)(ap + jc);
        avA[2 * kb + 1] = *(const int4*)(ap + (size_t)8 * NN + jc);
    }

    auto body = [&](int t, int4 (&cur)[8], int4 (&nxt)[8]) {
        // Prefetch adj for tile t+1 BEFORE the pipeline wait (full-tile lookahead)
        if (t + 1 < NT) {
            int jn = (t + 1) * 64 + 4 * c;
#pragma unroll
            for (int kb = 0; kb < 4; kb++) {
                nxt[2 * kb]     = *(const int4*)(ap + jn + kb * 16);
                nxt[2 * kb + 1] = *(const int4*)(ap + (size_t)8 * NN + jn + kb * 16);
            }
        }

        asm volatile("cp.async.wait_group 1;" ::: "memory");
        __syncthreads();

        // Stage B+E tile t+2 into the ring slot freed by compute(t-1)
        if (t + 2 < NT) {
            int s = (t + 2) % 3;
            const float* gsrc = gB + (size_t)(t + 2) * 4096;
#pragma unroll
            for (int i = 0; i < 8; i++)
                cp16(sbB + s * 16384 + (tid + i * 128) * 16,
                     gsrc + (size_t)(tid + i * 128) * 4);
            if (tid < 32)
                cp16(sbE + s * 512 + tid * 16, esrc + (t + 2) * 64);
        }
        asm volatile("cp.async.commit_group;" ::: "memory");

        const float* bB = sB + (t % 3) * 4096;
        const float* bE = sE + (t % 3) * 128;

#pragma unroll
        for (int kb = 0; kb < 4; kb++) {
            float4 vB = *(const float4*)(bE + kb * 16 + 4 * c);
            float4 vD = *(const float4*)(bE + 64 + kb * 16 + 4 * c);

            AF f0 = build_row(eA0, eC0, cur[2 * kb],     vB, vD, ls0);
            AF f1 = build_row(eA1, eC1, cur[2 * kb + 1], vB, vD, ls1);

            const float* bp = bB + bL + (kb << 10);
#pragma unroll
            for (int nb = 0; nb < 8; nb++) {
                float4 u = *(const float4*)(bp + (nb << 7));
                uint32_t Bh0 = __float_as_uint(u.x), Bh1 = __float_as_uint(u.y);
                uint32_t Bl0 = __float_as_uint(u.z), Bl1 = __float_as_uint(u.w);
                mma_bf16(acc[nb], f0.ha, f1.ha, f0.hb, f1.hb, Bh0, Bh1);
                mma_bf16(acc[nb], f0.ha, f1.ha, f0.hb, f1.hb, Bl0, Bl1);
                mma_bf16(acc[nb], f0.la, f1.la, f0.lb, f1.lb, Bh0, Bh1);
            }
        }
    };

    for (int t = 0; t < NT; t += 2) {
        body(t,     avA, avB);
        body(t + 1, avB, avA);
    }

    // Deterministic row-sum reduce within each k-quad (warp-local rows)
    ls0 += __shfl_xor_sync(0xFFFFFFFFu, ls0, 1);
    ls0 += __shfl_xor_sync(0xFFFFFFFFu, ls0, 2);
    ls1 += __shfl_xor_sync(0xFFFFFFFFu, ls1, 1);
    ls1 += __shfl_xor_sync(0xFFFFFFFFu, ls1, 2);

    // Epilogue: softmax divide, ELU, store
    float inv0 = 1.0f / ls0;
    float inv1 = 1.0f / ls1;
    float* o0 = out + (size_t)row0 * FOUT;
    float* o1 = out + (size_t)(row0 + 8) * FOUT;
#pragma unroll
    for (int nb = 0; nb < 8; nb++) {
        int col = nb * 8 + 2 * c;
        float x0 = acc[nb][0] * inv0, x1 = acc[nb][1] * inv0;
        float x2 = acc[nb][2] * inv1, x3 = acc[nb][3] * inv1;
        float2 oA, oB;
        oA.x = (x0 > 0.f) ? x0 : expm1f(x0);
        oA.y = (x1 > 0.f) ? x1 : expm1f(x1);
        oB.x = (x2 > 0.f) ? x2 : expm1f(x2);
        oB.y = (x3 > 0.f) ? x3 : expm1f(x3);
        *(float2*)(o0 + col) = oA;
        *(float2*)(o1 + col) = oB;
    }
}

// ---------------------------------------------------------------------------
// Inputs (metadata order): h[f32], adj[i32], W[f32], a[f32], bias[f32]
// Launch group is 4 kernels: ncu (-s 5, 2 pre-launch groups) captures
// index 3 = k_attn.
// ---------------------------------------------------------------------------
extern "C" void kernel_launch(void* const* d_in, const int* in_sizes, int n_in,
                              void* d_out, int out_size) {
    const float* h    = (const float*)d_in[0];
    const int*   adj  = (const int*)  d_in[1];
    const float* W    = (const float*)d_in[2];
    const float* a    = (const float*)d_in[3];
    const float* bias = (const float*)d_in[4];
    float* out = (float*)d_out;

    cudaFuncSetAttribute(k_attn, cudaFuncAttributeMaxDynamicSharedMemorySize,
                         SMEM_ATTN);

    k_init<<<1, 32>>>();
    k_proj<<<(BB * NN) / 64, 256>>>(h, W, a, bias);
    k_prep_pack<<<1024, 256>>>();
    k_attn<<<BB * (NN / 64), 128, SMEM_ATTN>>>(adj, out);
}

// round 15
// speedup vs baseline: 1.6938x; 1.1368x over previous
#include <cuda_runtime.h>
#include <cstdint>
#include <cstddef>

// Problem constants (fixed by the reference)
#define BB    4
#define NN    4096
#define FIN   256
#define FOUT  64
#define ALPHA 0.2f
#define NT    64              // j-tiles of 64

using u64 = unsigned long long;

// Scratch (device globals: no allocation allowed)
__device__ float g_Wh [BB * NN * FOUT];     // 4 MB, [b*N + j][f]
__device__ float g_Wh1[BB * NN];
__device__ float g_Wh2[BB * NN];
__device__ float g_max2[BB];
__device__ float g_eA[BB * NN];             // exp(w1 - m_i)
__device__ float g_eC[BB * NN];             // exp(a*w1 - m_i)
__device__ float g_eB[BB * NN];             // exp(w2)
__device__ float g_eD[BB * NN];             // exp(a*w2)
// Packed fragment-ready single-pass bf16 B: per (b,t) 512 units x 16B = 8KB
__device__ float g_Bpk[BB * NT * 2048];     // 2 MB

// ---------- packed f32x2 helpers (k_proj) ----------
__device__ __forceinline__ u64 pk2(float lo, float hi) {
    u64 r; asm("mov.b64 %0, {%1, %2};" : "=l"(r) : "f"(lo), "f"(hi)); return r;
}
__device__ __forceinline__ u64 fma2(u64 a, u64 b, u64 c) {
    u64 d; asm("fma.rn.f32x2 %0, %1, %2, %3;" : "=l"(d) : "l"(a), "l"(b), "l"(c)); return d;
}
__device__ __forceinline__ float2 upk2(u64 v) {
    float2 r; asm("mov.b64 {%0, %1}, %2;" : "=f"(r.x), "=f"(r.y) : "l"(v)); return r;
}

// bf16x2 pack: bits[31:16]=bf16(hi), bits[15:0]=bf16(lo)
__device__ __forceinline__ uint32_t cvt2(float hi, float lo) {
    uint32_t r; asm("cvt.rn.bf16x2.f32 %0, %1, %2;" : "=r"(r) : "f"(hi), "f"(lo)); return r;
}

// m16n8k16 bf16 MMA (baseline sm_80 ISA — compiles at compute_100)
__device__ __forceinline__ void mma_bf16(float* d, uint32_t a0, uint32_t a1,
                                         uint32_t a2, uint32_t a3,
                                         uint32_t b0, uint32_t b1) {
    asm volatile(
        "mma.sync.aligned.m16n8k16.row.col.f32.bf16.bf16.f32 "
        "{%0,%1,%2,%3}, {%4,%5,%6,%7}, {%8,%9}, {%0,%1,%2,%3};"
        : "+f"(d[0]), "+f"(d[1]), "+f"(d[2]), "+f"(d[3])
        : "r"(a0), "r"(a1), "r"(a2), "r"(a3), "r"(b0), "r"(b1));
}

__device__ __forceinline__ void cp16(uint32_t saddr, const void* g) {
    asm volatile("cp.async.cg.shared.global [%0], [%1], 16;"
                 :: "r"(saddr), "l"(g) : "memory");
}

// Order-independent (deterministic) float atomic max.
__device__ __forceinline__ void atomicMaxFloat(float* addr, float v) {
    if (v >= 0.f) atomicMax((int*)addr,          __float_as_int(v));
    else          atomicMin((unsigned int*)addr, __float_as_uint(v));
}

// ---------------------------------------------------------------------------
// K_init
// ---------------------------------------------------------------------------
__global__ void k_init() {
    if (threadIdx.x < BB) g_max2[threadIdx.x] = -3.0e38f;
}

// ---------------------------------------------------------------------------
// K_proj: tiled GEMM  Wh = h @ W + bias, fused Wh1/Wh2 dots + per-batch max.
// ---------------------------------------------------------------------------
__global__ void __launch_bounds__(256, 2)
k_proj(const float* __restrict__ h, const float* __restrict__ W,
       const float* __restrict__ a, const float* __restrict__ bias) {
    __shared__ __align__(16) float sH[64 * 68];
    __shared__ __align__(16) float sW[64 * 64];

    int tid = threadIdx.x;
    int ti = tid >> 4;
    int jq = tid & 15;
    int i0 = blockIdx.x * 64;

    u64 acc[4][2];
#pragma unroll
    for (int r = 0; r < 4; r++) { acc[r][0] = 0ull; acc[r][1] = 0ull; }

    for (int kc = 0; kc < 4; kc++) {
        int k0 = kc * 64;
#pragma unroll
        for (int u = 0; u < 4; u++) {
            int q = tid + u * 256;
            int row = q >> 4, c4 = q & 15;
            *(float4*)(sH + row * 68 + c4 * 4) =
                *(const float4*)(h + (size_t)(i0 + row) * FIN + k0 + c4 * 4);
            *(float4*)(sW + row * 64 + c4 * 4) =
                *(const float4*)(W + (size_t)(k0 + row) * FOUT + c4 * 4);
        }
        __syncthreads();

#pragma unroll 4
        for (int k = 0; k < 64; k++) {
            ulonglong2 wv = *(const ulonglong2*)(sW + k * 64 + 4 * jq);
#pragma unroll
            for (int r = 0; r < 4; r++) {
                float hv = sH[(ti * 4 + r) * 68 + k];
                u64 hh = pk2(hv, hv);
                acc[r][0] = fma2(hh, wv.x, acc[r][0]);
                acc[r][1] = fma2(hh, wv.y, acc[r][1]);
            }
        }
        __syncthreads();
    }

    float4 bv = *(const float4*)(bias + 4 * jq);
    float4 a1 = *(const float4*)(a + 4 * jq);
    float4 a2 = *(const float4*)(a + FOUT + 4 * jq);
    float p1[4], p2[4];
#pragma unroll
    for (int r = 0; r < 4; r++) {
        float2 v01 = upk2(acc[r][0]), v23 = upk2(acc[r][1]);
        float4 wh = make_float4(v01.x + bv.x, v01.y + bv.y,
                                v23.x + bv.z, v23.y + bv.w);
        int grow = i0 + ti * 4 + r;
        *(float4*)(g_Wh + (size_t)grow * FOUT + 4 * jq) = wh;
        p1[r] = wh.x * a1.x + wh.y * a1.y + wh.z * a1.z + wh.w * a1.w;
        p2[r] = wh.x * a2.x + wh.y * a2.y + wh.z * a2.z + wh.w * a2.w;
    }

    float* sR1 = sH;
    float* sR2 = sH + 1024;
#pragma unroll
    for (int r = 0; r < 4; r++) {
        sR1[jq * 64 + ti * 4 + r] = p1[r];
        sR2[jq * 64 + ti * 4 + r] = p2[r];
    }
    __syncthreads();
    if (tid < 64) {
        float w1 = 0.f, w2 = 0.f;
#pragma unroll
        for (int q = 0; q < 16; q++) {
            w1 += sR1[q * 64 + tid];
            w2 += sR2[q * 64 + tid];
        }
        g_Wh1[i0 + tid] = w1;
        g_Wh2[i0 + tid] = w2;
        float m = w2;
#pragma unroll
        for (int o = 16; o > 0; o >>= 1)
            m = fmaxf(m, __shfl_xor_sync(0xFFFFFFFFu, m, o));
        if ((tid & 31) == 0) atomicMaxFloat(&g_max2[i0 >> 12], m);
    }
}

// ---------------------------------------------------------------------------
// K_prep_pack: (a) factored attention exponentials (first 16384 threads);
// (b) one-time SINGLE-PASS bf16 fragment packing of Wh in the phase-aware
// permuted unit order (conflict-free LDS.128 in k_attn):
//   q = (r&1) | c<<1 | (r>>1)<<3 | nbp<<5 | kb<<7      (512 units per (b,t))
// Unit (16B) = {h01(f1), h23(f1), h01(f2), h23(f2)} where f1 = nbp*16 + r,
// f2 = f1 + 8; h01 = bf16x2 of Wh at j0,j0+1 (k=2c,2c+1), h23 at j0+2,j0+3
// (k=2c+8,2c+9), j0 = t*64 + kb*16 + 4c (j<->k permutation matches A side).
// ---------------------------------------------------------------------------
__global__ void k_prep_pack() {
    int idx = blockIdx.x * blockDim.x + threadIdx.x;   // 131072

    if (idx < BB * NN) {
        int b = idx >> 12;
        float mx = g_max2[b];
        float w1 = g_Wh1[idx];
        float w2 = g_Wh2[idx];
        float e = w1 + mx;
        float m = fmaxf(e, ALPHA * e);     // m_i >= all e_ij
        g_eA[idx] = __expf(w1 - m);
        g_eC[idx] = __expf(ALPHA * w1 - m);
        g_eB[idx] = __expf(w2);
        g_eD[idx] = __expf(ALPHA * w2);
    }

    int q    = idx & 511;
    int t    = (idx >> 9) & 63;
    int b    = idx >> 15;

    int r   = (q & 1) | (((q >> 3) & 3) << 1);
    int c   = (q >> 1) & 3;
    int nbp = (q >> 5) & 3;
    int kb  = (q >> 7) & 3;

    int j0 = t * 64 + kb * 16 + 4 * c;
    const float* src = g_Wh + (size_t)(b * NN + j0) * FOUT;
    int f1 = nbp * 16 + r;
    int f2 = f1 + 8;

    uint32_t h01a = cvt2(src[FOUT + f1],     src[f1]);
    uint32_t h23a = cvt2(src[3 * FOUT + f1], src[2 * FOUT + f1]);
    uint32_t h01b = cvt2(src[FOUT + f2],     src[f2]);
    uint32_t h23b = cvt2(src[3 * FOUT + f2], src[2 * FOUT + f2]);

    size_t u = ((size_t)(b * NT + t) * 512) + (size_t)q;
    *(uint4*)(g_Bpk + u * 4) = make_uint4(h01a, h23a, h01b, h23b);
}

// ---------------------------------------------------------------------------
// A-fragment builder (single pass): one row's 4 j's -> masked factored
// softmax weights rounded to bf16. ls accumulates the ROUNDED values so the
// softmax numerator and denominator use identical weights (exact softmax of
// logits perturbed by <= 2^-9 relative).
// ---------------------------------------------------------------------------
struct AF { uint32_t ha, hb; };
__device__ __forceinline__ AF build_row(float eA, float eC, int4 A,
                                        float4 vB, float4 vD, float& ls) {
    float p0 = (A.x > 0) ? fmaxf(eA * vB.x, eC * vD.x) : 0.f;
    float p1 = (A.y > 0) ? fmaxf(eA * vB.y, eC * vD.y) : 0.f;
    float p2 = (A.z > 0) ? fmaxf(eA * vB.z, eC * vD.z) : 0.f;
    float p3 = (A.w > 0) ? fmaxf(eA * vB.w, eC * vD.w) : 0.f;
    AF o;
    o.ha = cvt2(p1, p0);
    o.hb = cvt2(p3, p2);
    // Accumulate the rounded weights (consistency with the MMA numerator)
    float r0 = __uint_as_float(o.ha << 16);
    float r1 = __uint_as_float(o.ha & 0xFFFF0000u);
    float r2 = __uint_as_float(o.hb << 16);
    float r3 = __uint_as_float(o.hb & 0xFFFF0000u);
    ls += (r0 + r1) + (r2 + r3);
    return o;
}

// ---------------------------------------------------------------------------
// K_attn: fused masked-softmax attention; PV on m16n8k16 bf16, SINGLE PASS.
// CTA: 128 thr / 4 warps / 64 rows; warp w owns rows w*16..+15 x all 64 feats.
// B (packed bf16, permuted) + eB/eD factor slices stream via a 3-stage
// cp.async ring (25.5 KB static smem). Adjacency uses coalesced LDG.128 with
// a register double-buffer one full tile ahead. 32 MMAs per warp per tile.
// ---------------------------------------------------------------------------
__global__ void __launch_bounds__(128)
k_attn(const int* __restrict__ adj, float* __restrict__ out) {
    __shared__ __align__(16) float sB[3 * 2048];   // 24 KB B ring
    __shared__ __align__(16) float sE[3 * 128];    // 1.5 KB eB/eD ring
    uint32_t sbB = (uint32_t)__cvta_generic_to_shared(sB);
    uint32_t sbE = (uint32_t)__cvta_generic_to_shared(sE);

    int tid  = threadIdx.x;
    int lane = tid & 31;
    int w    = tid >> 5;
    int b    = blockIdx.x >> 6;                 // 64 blocks per batch
    int i0   = (blockIdx.x & 63) * 64;
    int r    = lane >> 2;                       // 0..7
    int c    = lane & 3;                        // 0..3

    int row0 = b * NN + i0 + w * 16 + r;        // global row (and +8)
    float eA0 = g_eA[row0],     eC0 = g_eC[row0];
    float eA1 = g_eA[row0 + 8], eC1 = g_eC[row0 + 8];

    const int*   ap  = adj + (size_t)row0 * NN;
    const float* eBb = g_eB + b * NN;
    const float* eDb = g_eD + b * NN;
    const float* gB  = g_Bpk + (size_t)(b * NT) * 2048;

    // eB/eD ring copy source for this thread (tid<32 copies one 16B unit)
    const float* esrc = (tid < 16) ? (eBb + (tid & 15) * 4)
                                   : (eDb + (tid & 15) * 4);

    // Consumer lane base into permuted B units (float offset = q*4)
    int bL = ((r & 1) | (c << 1) | ((r >> 1) << 3)) << 2;

    float acc[8][4];
#pragma unroll
    for (int nb = 0; nb < 8; nb++)
#pragma unroll
        for (int q = 0; q < 4; q++) acc[nb][q] = 0.f;
    float ls0 = 0.f, ls1 = 0.f;

    // Prologue: stage B+E tiles 0 and 1; load adj tile 0 into registers
#pragma unroll
    for (int pt = 0; pt < 2; pt++) {
#pragma unroll
        for (int i = 0; i < 4; i++)
            cp16(sbB + pt * 8192 + (tid + i * 128) * 16,
                 gB + (size_t)pt * 2048 + (size_t)(tid + i * 128) * 4);
        if (tid < 32)
            cp16(sbE + pt * 512 + tid * 16, esrc + pt * 64);
        asm volatile("cp.async.commit_group;" ::: "memory");
    }

    int4 avA[8], avB[8];
#pragma unroll
    for (int kb = 0; kb < 4; kb++) {
        int jc = kb * 16 + 4 * c;
        avA[2 * kb]     = *(const int4*)(ap + jc);
        avA[2 * kb + 1] = *(const int4*)(ap + (size_t)8 * NN + jc);
    }

    auto body = [&](int t, int4 (&cur)[8], int4 (&nxt)[8]) {
        // Prefetch adj for tile t+1 BEFORE the pipeline wait (full-tile lookahead)
        if (t + 1 < NT) {
            int jn = (t + 1) * 64 + 4 * c;
#pragma unroll
            for (int kb = 0; kb < 4; kb++) {
                nxt[2 * kb]     = *(const int4*)(ap + jn + kb * 16);
                nxt[2 * kb + 1] = *(const int4*)(ap + (size_t)8 * NN + jn + kb * 16);
            }
        }

        asm volatile("cp.async.wait_group 1;" ::: "memory");
        __syncthreads();

        // Stage B+E tile t+2 into the ring slot freed by compute(t-1)
        if (t + 2 < NT) {
            int s = (t + 2) % 3;
            const float* gsrc = gB + (size_t)(t + 2) * 2048;
#pragma unroll
            for (int i = 0; i < 4; i++)
                cp16(sbB + s * 8192 + (tid + i * 128) * 16,
                     gsrc + (size_t)(tid + i * 128) * 4);
            if (tid < 32)
                cp16(sbE + s * 512 + tid * 16, esrc + (t + 2) * 64);
        }
        asm volatile("cp.async.commit_group;" ::: "memory");

        const float* bB = sB + (t % 3) * 2048;
        const float* bE = sE + (t % 3) * 128;

#pragma unroll
        for (int kb = 0; kb < 4; kb++) {
            float4 vB = *(const float4*)(bE + kb * 16 + 4 * c);
            float4 vD = *(const float4*)(bE + 64 + kb * 16 + 4 * c);

            AF f0 = build_row(eA0, eC0, cur[2 * kb],     vB, vD, ls0);
            AF f1 = build_row(eA1, eC1, cur[2 * kb + 1], vB, vD, ls1);

            const float* bp = bB + bL + (kb << 9);
#pragma unroll
            for (int nbp = 0; nbp < 4; nbp++) {
                float4 u = *(const float4*)(bp + (nbp << 7));
                mma_bf16(acc[2 * nbp],     f0.ha, f1.ha, f0.hb, f1.hb,
                         __float_as_uint(u.x), __float_as_uint(u.y));
                mma_bf16(acc[2 * nbp + 1], f0.ha, f1.ha, f0.hb, f1.hb,
                         __float_as_uint(u.z), __float_as_uint(u.w));
            }
        }
    };

    for (int t = 0; t < NT; t += 2) {
        body(t,     avA, avB);
        body(t + 1, avB, avA);
    }

    // Deterministic row-sum reduce within each k-quad (warp-local rows)
    ls0 += __shfl_xor_sync(0xFFFFFFFFu, ls0, 1);
    ls0 += __shfl_xor_sync(0xFFFFFFFFu, ls0, 2);
    ls1 += __shfl_xor_sync(0xFFFFFFFFu, ls1, 1);
    ls1 += __shfl_xor_sync(0xFFFFFFFFu, ls1, 2);

    // Epilogue: softmax divide, ELU, store
    float inv0 = 1.0f / ls0;
    float inv1 = 1.0f / ls1;
    float* o0 = out + (size_t)row0 * FOUT;
    float* o1 = out + (size_t)(row0 + 8) * FOUT;
#pragma unroll
    for (int nb = 0; nb < 8; nb++) {
        int col = nb * 8 + 2 * c;
        float x0 = acc[nb][0] * inv0, x1 = acc[nb][1] * inv0;
        float x2 = acc[nb][2] * inv1, x3 = acc[nb][3] * inv1;
        float2 oA, oB;
        oA.x = (x0 > 0.f) ? x0 : expm1f(x0);
        oA.y = (x1 > 0.f) ? x1 : expm1f(x1);
        oB.x = (x2 > 0.f) ? x2 : expm1f(x2);
        oB.y = (x3 > 0.f) ? x3 : expm1f(x3);
        *(float2*)(o0 + col) = oA;
        *(float2*)(o1 + col) = oB;
    }
}

// ---------------------------------------------------------------------------
// Inputs (metadata order): h[f32], adj[i32], W[f32], a[f32], bias[f32]
// Launch group is 4 kernels: ncu (-s 5, 2 pre-launch groups) captures
// index 3 = k_attn.
// ---------------------------------------------------------------------------
extern "C" void kernel_launch(void* const* d_in, const int* in_sizes, int n_in,
                              void* d_out, int out_size) {
    const float* h    = (const float*)d_in[0];
    const int*   adj  = (const int*)  d_in[1];
    const float* W    = (const float*)d_in[2];
    const float* a    = (const float*)d_in[3];
    const float* bias = (const float*)d_in[4];
    float* out = (float*)d_out;

    k_init<<<1, 32>>>();
    k_proj<<<(BB * NN) / 64, 256>>>(h, W, a, bias);
    k_prep_pack<<<512, 256>>>();
    k_attn<<<BB * (NN / 64), 128>>>(adj, out);
}